// round 14
// baseline (speedup 1.0000x reference)
#include <cuda_runtime.h>
#include <cstdint>
#include <cstddef>

#define BB 2
#define LL 2048
#define HH 16
#define EE 64
#define BS 256
#define NB (LL / BS)                  // 8 blocks of 256
#define OUT_ELEMS (BB * LL * HH * EE) // output tensor precedes attn in d_out

// smem layout (floats) — XOR-swizzled, no padding. 64-row CTA, 4 CTAs/SM.
#define QT_OFF 0                      // Q^T: 64 e x 64 rows (16 quads, swizzled)
#define KTS_OFF 4096                  // K^T chunk (swizzled); aliased by S after GEMM1
#define SV_OFF 8192                   // V chunk: 64 keys x 64 cols (row-major)
#define SMEMF  12288                  // 49152 bytes -> 4 CTAs/SM (192KB)

typedef unsigned long long ull;

__device__ __forceinline__ ull pack2(float lo, float hi) {
    ull r;
    asm("mov.b64 %0, {%1, %2};" : "=l"(r) : "f"(lo), "f"(hi));
    return r;
}
__device__ __forceinline__ void unpack2(ull p, float &lo, float &hi) {
    asm("mov.b64 {%0, %1}, %2;" : "=f"(lo), "=f"(hi) : "l"(p));
}
__device__ __forceinline__ void fma2(ull &d, ull a, ull b) {
    asm("fma.rn.f32x2 %0, %1, %2, %0;" : "+l"(d) : "l"(a), "l"(b));
}

extern __shared__ float sm[];

__global__ void __launch_bounds__(256, 4)
sparse_attn_kernel(const float *__restrict__ Q,
                   const float *__restrict__ K,
                   const float *__restrict__ V,
                   float *__restrict__ out) {
    const int tid = threadIdx.x;
    const int bid = blockIdx.x;
    const int qf  = bid & 3;          // which 64-row quarter of the 256-block
    const int blk = (bid >> 2) & 7;
    const int h   = (bid >> 5) & 15;
    const int b   = bid >> 9;

    const int kg = tid & 31;   // key/col group (2 wide) — warp spans all kg
    const int rg = tid >> 5;   // row group: rows rg*8 .. rg*8+7 (local, 0..63)

    const float *Qrow = Q + ((size_t)(b * LL + blk * BS + qf * 64) * HH + h) * EE;
    const float *Krow = K + ((size_t)(b * LL + blk * BS) * HH + h) * EE;
    const float *Vrow = V + ((size_t)(b * LL + blk * BS) * HH + h) * EE;

    float *attnBase = out + (size_t)OUT_ELEMS + (size_t)(b * HH + h) * LL * LL +
                      (size_t)(blk * BS + qf * 64) * LL + (size_t)(blk * BS);
    float *attnCta  = out + (size_t)OUT_ELEMS + (size_t)(b * HH + h) * LL * LL +
                      (size_t)(blk * BS + qf * 64) * LL;
    const int blk64 = blk * 64;

    // ---- stage Q transposed with quad-swizzle: [e][rowquad ^ (e>>2)] ----
    #pragma unroll
    for (int i = 0; i < 4; i++) {
        int idx = i * 256 + tid;        // 1024 float4
        int r   = idx >> 4;             // 0..63
        int c4  = idx & 15;
        float4 f = *(const float4 *)(Qrow + r * 1024 + c4 * 4);
        const int q  = r >> 2;
        const int rl = r & 3;
        sm[QT_OFF + (c4 * 4 + 0) * 64 + ((q ^ c4) << 2) + rl] = f.x;
        sm[QT_OFF + (c4 * 4 + 1) * 64 + ((q ^ c4) << 2) + rl] = f.y;
        sm[QT_OFF + (c4 * 4 + 2) * 64 + ((q ^ c4) << 2) + rl] = f.z;
        sm[QT_OFF + (c4 * 4 + 3) * 64 + ((q ^ c4) << 2) + rl] = f.w;
    }

    ull accO[8];                        // accO[cc*4+rp]: col kg*2+cc, row-pair rp
    #pragma unroll
    for (int i = 0; i < 8; i++) accO[i] = 0ULL;
    float msum[8];
    #pragma unroll
    for (int i = 0; i < 8; i++) msum[i] = 0.f;

    for (int c = 0; c < 4; c++) {
        // ---- stage K^T chunk (swizzled, into KTS) and V chunk (row-major) ----
        #pragma unroll
        for (int i = 0; i < 4; i++) {
            int idx = i * 256 + tid;    // 1024 float4 per tensor
            int key = idx >> 4;
            int c4  = idx & 15;
            float4 f = *(const float4 *)(Krow + (size_t)(c * 64 + key) * 1024 + c4 * 4);
            const int kq = key >> 2;
            const int kl = key & 3;
            sm[KTS_OFF + (c4 * 4 + 0) * 64 + ((kq ^ c4) << 2) + kl] = f.x;
            sm[KTS_OFF + (c4 * 4 + 1) * 64 + ((kq ^ c4) << 2) + kl] = f.y;
            sm[KTS_OFF + (c4 * 4 + 2) * 64 + ((kq ^ c4) << 2) + kl] = f.z;
            sm[KTS_OFF + (c4 * 4 + 3) * 64 + ((kq ^ c4) << 2) + kl] = f.w;
            float4 g = *(const float4 *)(Vrow + (size_t)(c * 64 + key) * 1024 + c4 * 4);
            *(float4 *)(sm + SV_OFF + key * 64 + c4 * 4) = g;
        }
        // ---- interleaved zero-fill: 16 rows x 448 f4 per chunk ----
        {
            const int cx = tid & 15;
            float *zp = attnCta + (size_t)(c * 16 + (tid >> 4)) * LL;
            #pragma unroll 7
            for (int j = 0; j < 28; j++) {
                int c4 = j * 16 + cx;
                c4 = (c4 >= blk64) ? c4 + 64 : c4;
                __stcs((float4 *)(zp + c4 * 4), make_float4(0.f, 0.f, 0.f, 0.f));
            }
        }
        __syncthreads();   // KTS/SV staged; prev GEMM2 done

        // ---- GEMM1: S = Q . K^T  (thread tile 8 rows x 2 keys) ----
        ull acc[8];        // acc[k*4+rp]
        #pragma unroll
        for (int i = 0; i < 8; i++) acc[i] = 0ULL;
        #pragma unroll 4
        for (int x = 0; x < 16; x++) {
            const float *qa = sm + QT_OFF + x * 256 + (((2 * rg)     ^ x) << 2);
            const float *qb = sm + QT_OFF + x * 256 + (((2 * rg + 1) ^ x) << 2);
            const float *kb = sm + KTS_OFF + x * 256 + (((kg >> 1) ^ x) << 2) + (kg & 1) * 2;
            #pragma unroll
            for (int ee = 0; ee < 4; ee++) {
                ulonglong2 qA = *(const ulonglong2 *)(qa + ee * 64); // rows 8rg..+3
                ulonglong2 qB = *(const ulonglong2 *)(qb + ee * 64); // rows 8rg+4..+7
                ull kd = *(const ull *)(kb + ee * 64);               // {K[2kg],K[2kg+1]}
                float k0, k1;
                unpack2(kd, k0, k1);
                ull kd0 = pack2(k0, k0);
                ull kd1 = pack2(k1, k1);
                fma2(acc[0], qA.x, kd0); fma2(acc[1], qA.y, kd0);
                fma2(acc[2], qB.x, kd0); fma2(acc[3], qB.y, kd0);
                fma2(acc[4], qA.x, kd1); fma2(acc[5], qA.y, kd1);
                fma2(acc[6], qB.x, kd1); fma2(acc[7], qB.y, kd1);
            }
        }
        // ---- epilogue (registers only): exp, row partial sums, attn STG ----
        float ev[2][8];
        {
            #pragma unroll
            for (int k = 0; k < 2; k++)
                #pragma unroll
                for (int rp = 0; rp < 4; rp++)
                    unpack2(acc[k * 4 + rp], ev[k][2 * rp], ev[k][2 * rp + 1]);
            #pragma unroll
            for (int k = 0; k < 2; k++)
                #pragma unroll
                for (int rr = 0; rr < 8; rr++)
                    ev[k][rr] = __expf(ev[k][rr]);   // no-max softmax: |s| bounded
            #pragma unroll
            for (int rr = 0; rr < 8; rr++)
                msum[rr] += ev[0][rr] + ev[1][rr];

            // attn diag: cols (2kg, 2kg+1) of 8 rows — 256B/warp coalesced STG.64
            float *arow = attnBase + (size_t)(rg * 8) * LL + c * 64 + kg * 2;
            #pragma unroll
            for (int rr = 0; rr < 8; rr++)
                *(ull *)(arow + (size_t)rr * LL) = pack2(ev[0][rr], ev[1][rr]);
        }
        __syncthreads();   // ALL warps done reading K from KTS -> safe to alias S

        // ---- S -> smem (into KTS alias) ----
        #pragma unroll
        for (int k = 0; k < 2; k++) {
            const int key = kg * 2 + k;
            float *spb = sm + KTS_OFF + key * 64;
            const int kq = key >> 2;
            *(float4 *)(spb + (((2 * rg)     ^ kq) << 2)) =
                make_float4(ev[k][0], ev[k][1], ev[k][2], ev[k][3]);
            *(float4 *)(spb + (((2 * rg + 1) ^ kq) << 2)) =
                make_float4(ev[k][4], ev[k][5], ev[k][6], ev[k][7]);
        }
        // S row-quads 2rg/2rg+1 are produced and consumed by warp rg only
        __syncwarp(0xffffffffu);

        // ---- GEMM2: O += S . V  (thread tile 8 rows x 2 cols) ----
        #pragma unroll 4
        for (int x = 0; x < 16; x++) {
            const float *sa = sm + KTS_OFF + x * 256 + (((2 * rg)     ^ x) << 2);
            const float *sb = sm + KTS_OFF + x * 256 + (((2 * rg + 1) ^ x) << 2);
            const float *vb = sm + SV_OFF + x * 256 + kg * 2;
            #pragma unroll
            for (int kk = 0; kk < 4; kk++) {
                ulonglong2 sA = *(const ulonglong2 *)(sa + kk * 64);
                ulonglong2 sB = *(const ulonglong2 *)(sb + kk * 64);
                ull vd = *(const ull *)(vb + kk * 64);   // {V[k][2kg], V[k][2kg+1]}
                float v0, v1;
                unpack2(vd, v0, v1);
                ull vd0 = pack2(v0, v0);
                ull vd1 = pack2(v1, v1);
                fma2(accO[0], sA.x, vd0); fma2(accO[1], sA.y, vd0);
                fma2(accO[2], sB.x, vd0); fma2(accO[3], sB.y, vd0);
                fma2(accO[4], sA.x, vd1); fma2(accO[5], sA.y, vd1);
                fma2(accO[6], sB.x, vd1); fma2(accO[7], sB.y, vd1);
            }
        }
        __syncthreads();   // all warps done reading S/V before next staging
    }

    // ---- row sums: butterfly over all 32 kg lanes ----
    float rec[8];
    #pragma unroll
    for (int rr = 0; rr < 8; rr++) {
        float v = msum[rr];
        v += __shfl_xor_sync(0xffffffffu, v, 1);
        v += __shfl_xor_sync(0xffffffffu, v, 2);
        v += __shfl_xor_sync(0xffffffffu, v, 4);
        v += __shfl_xor_sync(0xffffffffu, v, 8);
        v += __shfl_xor_sync(0xffffffffu, v, 16);
        rec[rr] = 1.0f / v;
    }

    // ---- O write: 8 rows x this thread's 2 E-cols (256B/warp per row) ----
    #pragma unroll
    for (int rp = 0; rp < 4; rp++) {
        float a0, a1, b0, b1;
        unpack2(accO[rp],     a0, a1);   // col0: rows 2rp, 2rp+1
        unpack2(accO[4 + rp], b0, b1);   // col1: rows 2rp, 2rp+1
        const int r0 = blk * BS + qf * 64 + rg * 8 + 2 * rp;
        float rc0 = rec[2 * rp], rc1 = rec[2 * rp + 1];
        __stcs((ull *)(out + ((size_t)(b * LL + r0) * HH + h) * EE + kg * 2),
               pack2(a0 * rc0, b0 * rc0));
        __stcs((ull *)(out + ((size_t)(b * LL + r0 + 1) * HH + h) * EE + kg * 2),
               pack2(a1 * rc1, b1 * rc1));
    }

    // ---- normalize attn diag rows in place (L2-hot) ----
    #pragma unroll
    for (int c = 0; c < 4; c++) {
        float *arow = attnBase + (size_t)(rg * 8) * LL + c * 64 + kg * 2;
        #pragma unroll
        for (int rr = 0; rr < 8; rr++) {
            ull p = *(ull *)(arow + (size_t)rr * LL);
            float lo, hi;
            unpack2(p, lo, hi);
            float rc = rec[rr];
            *(ull *)(arow + (size_t)rr * LL) = pack2(lo * rc, hi * rc);
        }
    }
}

extern "C" void kernel_launch(void *const *d_in, const int *in_sizes, int n_in,
                              void *d_out, int out_size) {
    const float *Q = (const float *)d_in[0];
    const float *K = (const float *)d_in[1];
    const float *V = (const float *)d_in[2];
    float *out = (float *)d_out;

    const int smem_bytes = SMEMF * (int)sizeof(float); // 49152
    cudaFuncSetAttribute(sparse_attn_kernel,
                         cudaFuncAttributeMaxDynamicSharedMemorySize, smem_bytes);
    sparse_attn_kernel<<<BB * HH * NB * 4, 256, smem_bytes>>>(Q, K, V, out);
}